// round 9
// baseline (speedup 1.0000x reference)
#include <cuda_runtime.h>
#include <cuda_bf16.h>
#include <cstdint>

namespace {
constexpr int kT     = 79;
constexpr int kBM    = 128;            // batch rows per CTA
constexpr int kTH    = 512;            // 16 warps: wm = w&3 (rows), wn = w>>2 (cols)
constexpr int NROUND = 79;             // 78 recurrence GEMMs + 1 output GEMM
constexpr int NCH    = 16;             // k=16 chunks per 256-K GEMM
constexpr int TOTAL_CH = NROUND * NCH; // 1264
constexpr int NSTAGE = 4;              // ring depth per quad

// smem layout (bytes)
constexpr int SM_HHI = 0;                       // h hi [128][512B] swizzled
constexpr int SM_HLO = 65536;                   // h lo
constexpr int SM_B   = 131072;                  // 4 quads x 4 stages x 4KB
constexpr int SM_WT  = 196608;                  // float4[256] = (W0,W1,W2,b_rnn)
constexpr int SM_MB  = 200704;                  // full[4][4] then empty[4][4]
constexpr int SMEM_BYTES = SM_MB + 512;         // 201216
}

// Pre-split B operands (row-major [k][n] like U), bf16 hi/lo.
__device__ __align__(16) unsigned char g_Uh[131072];
__device__ __align__(16) unsigned char g_Ul[131072];
__device__ __align__(16) unsigned char g_Wh[131072];
__device__ __align__(16) unsigned char g_Wl[131072];

// ---------------- PTX helpers ----------------
__device__ __forceinline__ void ldsm4(uint32_t (&r)[4], uint32_t a) {
    asm volatile("ldmatrix.sync.aligned.m8n8.x4.shared.b16 {%0,%1,%2,%3}, [%4];"
                 : "=r"(r[0]), "=r"(r[1]), "=r"(r[2]), "=r"(r[3]) : "r"(a));
}
__device__ __forceinline__ void ldsm4t(uint32_t (&r)[4], uint32_t a) {
    asm volatile("ldmatrix.sync.aligned.m8n8.x4.trans.shared.b16 {%0,%1,%2,%3}, [%4];"
                 : "=r"(r[0]), "=r"(r[1]), "=r"(r[2]), "=r"(r[3]) : "r"(a));
}
__device__ __forceinline__ void mma16816(float (&d)[4], const uint32_t (&a)[4],
                                         uint32_t b0, uint32_t b1) {
    asm volatile(
        "mma.sync.aligned.m16n8k16.row.col.f32.bf16.bf16.f32 "
        "{%0,%1,%2,%3}, {%4,%5,%6,%7}, {%8,%9}, {%0,%1,%2,%3};"
        : "+f"(d[0]), "+f"(d[1]), "+f"(d[2]), "+f"(d[3])
        : "r"(a[0]), "r"(a[1]), "r"(a[2]), "r"(a[3]), "r"(b0), "r"(b1));
}
__device__ __forceinline__ void cpa16(uint32_t d, const void* s) {
    asm volatile("cp.async.cg.shared.global [%0], [%1], 16;" :: "r"(d), "l"(s));
}
__device__ __forceinline__ void cp_mbar_arrive(uint32_t a) {
    asm volatile("cp.async.mbarrier.arrive.noinc.shared.b64 [%0];"
                 :: "r"(a) : "memory");
}
__device__ __forceinline__ void mbar_init(uint32_t a, uint32_t cnt) {
    asm volatile("mbarrier.init.shared.b64 [%0], %1;" :: "r"(a), "r"(cnt) : "memory");
}
__device__ __forceinline__ void mbar_arrive(uint32_t a) {
    asm volatile("mbarrier.arrive.shared.b64 _, [%0];" :: "r"(a) : "memory");
}
__device__ __forceinline__ void mbar_wait(uint32_t a, uint32_t phase) {
    asm volatile(
        "{\n\t.reg .pred P;\n"
        "W%=:\n\t"
        "mbarrier.try_wait.parity.shared::cta.b64 P, [%0], %1;\n\t"
        "@!P bra W%=;\n\t}"
        :: "r"(a), "r"(phase) : "memory");
}
__device__ __forceinline__ void st32s(uint32_t a, uint32_t v) {
    asm volatile("st.shared.b32 [%0], %1;" :: "r"(a), "r"(v));
}
__device__ __forceinline__ void barx(int id) {
    asm volatile("bar.sync %0, 128;" :: "r"(id) : "memory");
}
// pack: low 16 = bf16(v0), high 16 = bf16(v1)
__device__ __forceinline__ uint32_t cvt_pack(float v0, float v1) {
    uint32_t r;
    asm("cvt.rn.bf16x2.f32 %0, %1, %2;" : "=r"(r) : "f"(v1), "f"(v0));
    return r;
}

// ---------------- prep: split U / Wd into bf16 hi/lo blobs ----------------
__global__ void prep_kernel(const float* __restrict__ U, const float* __restrict__ Wd) {
    const int idx = blockIdx.x * 256 + threadIdx.x;         // 65536 elems
    {
        const float v = U[idx];
        const __nv_bfloat16 h = __float2bfloat16(v);
        ((__nv_bfloat16*)g_Uh)[idx] = h;
        ((__nv_bfloat16*)g_Ul)[idx] = __float2bfloat16(v - __bfloat162float(h));
    }
    {
        const float v = Wd[idx];
        const __nv_bfloat16 h = __float2bfloat16(v);
        ((__nv_bfloat16*)g_Wh)[idx] = h;
        ((__nv_bfloat16*)g_Wl)[idx] = __float2bfloat16(v - __bfloat162float(h));
    }
}

// ---------------- main fused RNN kernel (HMMA, mbarrier-ringed B) ----------------
__global__ void __launch_bounds__(kTH, 1)
rnn_hmma_kernel(const float* __restrict__ x0, const float* __restrict__ x1,
                const float* __restrict__ x2, const float* __restrict__ Win,
                const float* __restrict__ brnn, const float* __restrict__ bd,
                float* __restrict__ out) {
    extern __shared__ unsigned char smem[];
    const uint32_t sb = (uint32_t)__cvta_generic_to_shared(smem);

    const int tid = threadIdx.x;
    const int w   = tid >> 5;
    const int L   = tid & 31;
    const int wm  = w & 3;                 // row-group (32 m-rows)
    const int wn  = w >> 2;                // quad (64 n-cols); quad tids contiguous
    const int gid = L >> 2;
    const int tig = L & 3;
    const int b0  = blockIdx.x * kBM;

    // mbarrier addresses for this quad
    const uint32_t fmb0 = sb + SM_MB + (uint32_t)wn * 32;          // full[s]
    const uint32_t emb0 = sb + SM_MB + 128 + (uint32_t)wn * 32;    // empty[s]

    // stage proj table (W0,W1,W2,b_rnn per col)
    if (tid < 256) {
        float4 wv = make_float4(Win[tid], Win[256 + tid], Win[512 + tid], brnn[tid]);
        *reinterpret_cast<float4*>(smem + SM_WT + tid * 16) = wv;
    }
    if (tid == 0) {
        #pragma unroll
        for (int q = 0; q < 4; q++)
            #pragma unroll
            for (int s = 0; s < NSTAGE; s++) {
                mbar_init(sb + SM_MB + q * 32 + s * 8, 128);       // full
                mbar_init(sb + SM_MB + 128 + q * 32 + s * 8, 4);   // empty
            }
    }

    // lane-invariant pieces for swizzled ldmatrix addressing
    const int arow   = wm * 32 + (L & 15);                 // A row (first 16-row tile)
    const uint32_t axor = (uint32_t)((arow & 7) << 4);
    const uint32_t aseg = (uint32_t)((L >> 4) * 16);
    const uint32_t aHi  = sb + SM_HHI + (uint32_t)arow * 512;
    const uint32_t aLo  = sb + SM_HLO + (uint32_t)arow * 512;
    const int brow   = L & 15;                             // B k-row within 16
    const uint32_t bxor = (uint32_t)((brow & 7) << 4);
    const uint32_t bseg = (uint32_t)((L >> 4) * 16);
    const uint32_t bRow = (uint32_t)brow * 128;

    // stage one k=16 chunk slice (hi 2KB + lo 2KB) into ring stage gi&3
    auto issue_chunk = [&](int gi) {
        const bool lastR = gi >= (NROUND - 1) * NCH;
        const int cc = gi & 15;
        const uint32_t dst = sb + SM_B + (uint32_t)wn * 16384u
                           + (uint32_t)(gi & 3) * 4096u;
        const int lt  = tid & 127;
        const int row = lt >> 3;                 // 0..15
        const int seg = (lt & 7) * 16;           // 0..112
        const int sofs = (cc * 16 + row) * 512 + wn * 128 + seg;
        const uint32_t dofs = (uint32_t)(row * 128 + (seg ^ ((row & 7) << 4)));
        cpa16(dst + dofs,        (lastR ? g_Wh : g_Uh) + sofs);
        cpa16(dst + 2048 + dofs, (lastR ? g_Wl : g_Ul) + sofs);
        cp_mbar_arrive(fmb0 + (uint32_t)(gi & 3) * 8);
    };

    float acc[2][8][4];

    auto do_chunk = [&](int c, uint32_t qb) {
        const uint32_t ak = ((uint32_t)(c * 32) + aseg) ^ axor;
        uint32_t ahi[2][4], alo[2][4];
        ldsm4(ahi[0], aHi + ak);
        ldsm4(ahi[1], aHi + 8192 + ak);
        ldsm4(alo[0], aLo + ak);
        ldsm4(alo[1], aLo + 8192 + ak);
        #pragma unroll
        for (int g = 0; g < 4; g++) {
            uint32_t bh[4], bl[4];
            const uint32_t ba = qb + bRow + (((uint32_t)(g * 32) + bseg) ^ bxor);
            ldsm4t(bh, ba);
            ldsm4t(bl, ba + 2048);
            mma16816(acc[0][2 * g],     ahi[0], bh[0], bh[1]);
            mma16816(acc[1][2 * g],     ahi[1], bh[0], bh[1]);
            mma16816(acc[0][2 * g + 1], ahi[0], bh[2], bh[3]);
            mma16816(acc[1][2 * g + 1], ahi[1], bh[2], bh[3]);
            mma16816(acc[0][2 * g],     alo[0], bh[0], bh[1]);
            mma16816(acc[1][2 * g],     alo[1], bh[0], bh[1]);
            mma16816(acc[0][2 * g + 1], alo[0], bh[2], bh[3]);
            mma16816(acc[1][2 * g + 1], alo[1], bh[2], bh[3]);
            mma16816(acc[0][2 * g],     ahi[0], bl[0], bl[1]);
            mma16816(acc[1][2 * g],     ahi[1], bl[0], bl[1]);
            mma16816(acc[0][2 * g + 1], ahi[0], bl[2], bl[3]);
            mma16816(acc[1][2 * g + 1], ahi[1], bl[2], bl[3]);
        }
    };

    // epilogue: h = relu(proj(col) [+ D]); split to bf16 hi/lo in swizzled smem
    float xs0[4], xs1[4], xs2[4];
    auto load_xs = [&](int col) {
        #pragma unroll
        for (int q = 0; q < 4; q++) {
            const int row = wm * 32 + (q >> 1) * 16 + (q & 1) * 8 + gid;
            const int idx = (b0 + row) * kT + col;
            xs0[q] = __ldg(x0 + idx);
            xs1[q] = __ldg(x1 + idx);
            xs2[q] = __ldg(x2 + idx);
        }
    };
    auto epilogue = [&](bool addD) {
        #pragma unroll
        for (int nt = 0; nt < 8; nt++) {
            const int cb = wn * 64 + nt * 8 + 2 * tig;
            const float4 wA = *reinterpret_cast<const float4*>(smem + SM_WT + cb * 16);
            const float4 wB = *reinterpret_cast<const float4*>(smem + SM_WT + cb * 16 + 16);
            #pragma unroll
            for (int mt = 0; mt < 2; mt++)
            #pragma unroll
            for (int hf = 0; hf < 2; hf++) {
                const int q = mt * 2 + hf;
                float v0 = wA.w + xs0[q] * wA.x + xs1[q] * wA.y + xs2[q] * wA.z;
                float v1 = wB.w + xs0[q] * wB.x + xs1[q] * wB.y + xs2[q] * wB.z;
                if (addD) {
                    v0 += acc[mt][nt][hf * 2];
                    v1 += acc[mt][nt][hf * 2 + 1];
                }
                v0 = fmaxf(v0, 0.f);
                v1 = fmaxf(v1, 0.f);
                const uint32_t hp = cvt_pack(v0, v1);
                const float h0 = __uint_as_float(hp << 16);
                const float h1 = __uint_as_float(hp & 0xFFFF0000u);
                const uint32_t lp = cvt_pack(v0 - h0, v1 - h1);
                const int row = wm * 32 + mt * 16 + hf * 8 + gid;
                const uint32_t off =
                    (uint32_t)(row * 512 + ((cb * 2) ^ ((row & 7) << 4)));
                st32s(sb + SM_HHI + off, hp);
                st32s(sb + SM_HLO + off, lp);
            }
        }
    };

    // ---- prologue ----
    __syncthreads();                       // mbar init + proj table visible
    issue_chunk(0);
    issue_chunk(1);
    issue_chunk(2);
    issue_chunk(3);
    load_xs(kT - 1);
    epilogue(false);                       // h1 = relu(proj(col 78)), h0 = 0
    barx(1 + wm);                          // h rows wm visible to row-group

    // ---- rounds ----
    #pragma unroll 1
    for (int r = 0; r < NROUND; r++) {
        if (r < NROUND - 1) load_xs(kT - 2 - r);
        #pragma unroll
        for (int mt = 0; mt < 2; mt++)
            #pragma unroll
            for (int nt = 0; nt < 8; nt++)
                #pragma unroll
                for (int e = 0; e < 4; e++) acc[mt][nt][e] = 0.f;

        const int gbase = r * NCH;
        #pragma unroll 4
        for (int c = 0; c < NCH; c++) {
            const int gi = gbase + c;
            const int s  = gi & 3;
            const uint32_t ph = (uint32_t)((gi >> 2) & 1);
            mbar_wait(fmb0 + (uint32_t)s * 8, ph);              // chunk data ready
            do_chunk(c, sb + SM_B + (uint32_t)wn * 16384u + (uint32_t)s * 4096u);
            if (L == 0) mbar_arrive(emb0 + (uint32_t)s * 8);    // warp reads done
            const int gi2 = gi + NSTAGE;
            if (gi2 < TOTAL_CH) {
                mbar_wait(emb0 + (uint32_t)s * 8, ph);          // stage freed by quad
                issue_chunk(gi2);
            }
        }

        barx(1 + wm);                      // row-group: A reads of rows wm done
        if (r < NROUND - 1) {
            epilogue(true);                // h_{t+1}
            barx(1 + wm);                  // h rows wm written
        } else {
            // out = D + b_d
            #pragma unroll
            for (int nt = 0; nt < 8; nt++) {
                const int cb = wn * 64 + nt * 8 + 2 * tig;
                const float bd0 = __ldg(bd + cb);
                const float bd1 = __ldg(bd + cb + 1);
                #pragma unroll
                for (int mt = 0; mt < 2; mt++)
                #pragma unroll
                for (int hf = 0; hf < 2; hf++) {
                    const int row = wm * 32 + mt * 16 + hf * 8 + gid;
                    float2 o;
                    o.x = acc[mt][nt][hf * 2]     + bd0;
                    o.y = acc[mt][nt][hf * 2 + 1] + bd1;
                    *reinterpret_cast<float2*>(out + (size_t)(b0 + row) * 256 + cb) = o;
                }
            }
        }
    }
}

extern "C" void kernel_launch(void* const* d_in, const int* in_sizes, int n_in,
                              void* d_out, int out_size) {
    const float* x0   = (const float*)d_in[0];
    const float* x1   = (const float*)d_in[1];
    const float* x2   = (const float*)d_in[2];
    const float* Win  = (const float*)d_in[3];
    const float* U    = (const float*)d_in[4];
    const float* brnn = (const float*)d_in[5];
    const float* Wd   = (const float*)d_in[6];
    const float* bd   = (const float*)d_in[7];
    float* out = (float*)d_out;

    prep_kernel<<<256, 256>>>(U, Wd);

    cudaFuncSetAttribute(rnn_hmma_kernel,
                         cudaFuncAttributeMaxDynamicSharedMemorySize, SMEM_BYTES);
    rnn_hmma_kernel<<<16384 / kBM, kTH, SMEM_BYTES>>>(x0, x1, x2, Win, brnn, bd, out);
}

// round 13
// speedup vs baseline: 1.0212x; 1.0212x over previous
#include <cuda_runtime.h>
#include <cuda_bf16.h>
#include <cstdint>

namespace {
constexpr int kT     = 79;
constexpr int kBM    = 64;             // batch rows per CTA
constexpr int kTH    = 256;            // 8 warps: wm = w&1 (rows), wn = w>>1 (cols)
constexpr int NROUND = 79;             // 78 recurrence GEMMs + 1 output GEMM
constexpr int NCH    = 16;             // k=16 chunks per 256-K GEMM
constexpr int TOTAL_CH = NROUND * NCH; // 1264

// smem layout (bytes) per CTA
constexpr int SM_HHI = 0;                       // h hi [64][512B] swizzled
constexpr int SM_HLO = 32768;                   // h lo
constexpr int SM_B   = 65536;                   // 4 groups x 2 stages x 4KB
constexpr int SM_WT  = 98304;                   // float4[256] = (W0,W1,W2,b_rnn)
constexpr int SMEM_BYTES = SM_WT + 4096;        // 102400
}

// Pre-split B operands (row-major [k][n] like U), bf16 hi/lo.
__device__ __align__(16) unsigned char g_Uh[131072];
__device__ __align__(16) unsigned char g_Ul[131072];
__device__ __align__(16) unsigned char g_Wh[131072];
__device__ __align__(16) unsigned char g_Wl[131072];

// ---------------- PTX helpers ----------------
__device__ __forceinline__ void ldsm4(uint32_t (&r)[4], uint32_t a) {
    asm volatile("ldmatrix.sync.aligned.m8n8.x4.shared.b16 {%0,%1,%2,%3}, [%4];"
                 : "=r"(r[0]), "=r"(r[1]), "=r"(r[2]), "=r"(r[3]) : "r"(a));
}
__device__ __forceinline__ void ldsm4t(uint32_t (&r)[4], uint32_t a) {
    asm volatile("ldmatrix.sync.aligned.m8n8.x4.trans.shared.b16 {%0,%1,%2,%3}, [%4];"
                 : "=r"(r[0]), "=r"(r[1]), "=r"(r[2]), "=r"(r[3]) : "r"(a));
}
__device__ __forceinline__ void mma16816(float (&d)[4], const uint32_t (&a)[4],
                                         uint32_t b0, uint32_t b1) {
    asm volatile(
        "mma.sync.aligned.m16n8k16.row.col.f32.bf16.bf16.f32 "
        "{%0,%1,%2,%3}, {%4,%5,%6,%7}, {%8,%9}, {%0,%1,%2,%3};"
        : "+f"(d[0]), "+f"(d[1]), "+f"(d[2]), "+f"(d[3])
        : "r"(a[0]), "r"(a[1]), "r"(a[2]), "r"(a[3]), "r"(b0), "r"(b1));
}
__device__ __forceinline__ void cpa16(uint32_t d, const void* s) {
    asm volatile("cp.async.cg.shared.global [%0], [%1], 16;" :: "r"(d), "l"(s));
}
__device__ __forceinline__ void cp_commit() {
    asm volatile("cp.async.commit_group;" ::: "memory");
}
__device__ __forceinline__ void st32s(uint32_t a, uint32_t v) {
    asm volatile("st.shared.b32 [%0], %1;" :: "r"(a), "r"(v));
}
__device__ __forceinline__ void bar128(int id) {
    asm volatile("bar.sync %0, 128;" :: "r"(id) : "memory");
}
__device__ __forceinline__ void bar64(int id) {
    asm volatile("bar.sync %0, 64;" :: "r"(id) : "memory");
}
// pack: low 16 = bf16(v0), high 16 = bf16(v1)
__device__ __forceinline__ uint32_t cvt_pack(float v0, float v1) {
    uint32_t r;
    asm("cvt.rn.bf16x2.f32 %0, %1, %2;" : "=r"(r) : "f"(v1), "f"(v0));
    return r;
}

// ---------------- prep: split U / Wd into bf16 hi/lo blobs ----------------
__global__ void prep_kernel(const float* __restrict__ U, const float* __restrict__ Wd) {
    const int idx = blockIdx.x * 256 + threadIdx.x;         // 65536 elems
    {
        const float v = U[idx];
        const __nv_bfloat16 h = __float2bfloat16(v);
        ((__nv_bfloat16*)g_Uh)[idx] = h;
        ((__nv_bfloat16*)g_Ul)[idx] = __float2bfloat16(v - __bfloat162float(h));
    }
    {
        const float v = Wd[idx];
        const __nv_bfloat16 h = __float2bfloat16(v);
        ((__nv_bfloat16*)g_Wh)[idx] = h;
        ((__nv_bfloat16*)g_Wl)[idx] = __float2bfloat16(v - __bfloat162float(h));
    }
}

// ---------------- main fused RNN kernel (HMMA, 2 CTAs/SM) ----------------
__global__ void __launch_bounds__(kTH, 2)
rnn_hmma_kernel(const float* __restrict__ x0, const float* __restrict__ x1,
                const float* __restrict__ x2, const float* __restrict__ Win,
                const float* __restrict__ brnn, const float* __restrict__ bd,
                float* __restrict__ out) {
    extern __shared__ unsigned char smem[];
    const uint32_t sb = (uint32_t)__cvta_generic_to_shared(smem);

    const int tid = threadIdx.x;
    const int w   = tid >> 5;
    const int L   = tid & 31;
    const int wm  = w & 1;                 // row-group (32 m-rows)
    const int wn  = w >> 1;                // col-group (64 n-cols); 2 warps each
    const int gid = L >> 2;
    const int tig = L & 3;
    const int b0  = blockIdx.x * kBM;

    // stage proj table (W0,W1,W2,b_rnn per col)
    if (tid < 256) {
        float4 wv = make_float4(Win[tid], Win[256 + tid], Win[512 + tid], brnn[tid]);
        *reinterpret_cast<float4*>(smem + SM_WT + tid * 16) = wv;
    }

    // lane-invariant pieces for swizzled ldmatrix addressing
    const int arow   = wm * 32 + (L & 15);                 // A row (first 16-row tile)
    const uint32_t axor = (uint32_t)((arow & 7) << 4);
    const uint32_t aseg = (uint32_t)((L >> 4) * 16);
    const uint32_t aHi  = sb + SM_HHI + (uint32_t)arow * 512;
    const uint32_t aLo  = sb + SM_HLO + (uint32_t)arow * 512;
    const int brow   = L & 15;                             // B k-row within 16
    const uint32_t bxor = (uint32_t)((brow & 7) << 4);
    const uint32_t bseg = (uint32_t)((L >> 4) * 16);
    const uint32_t bRow = (uint32_t)brow * 128;

    // group-private B stream: one k=16 chunk slice (hi 2KB + lo 2KB), 64 threads
    auto issue_chunk = [&](int gi) {
        const bool lastR = gi >= (NROUND - 1) * NCH;
        const int cc = gi & 15;
        const uint32_t dst = sb + SM_B + (uint32_t)wn * 8192u
                           + (uint32_t)(gi & 1) * 4096u;
        const int lt = tid & 63;
        #pragma unroll
        for (int i = 0; i < 2; i++) {
            const int u   = lt * 2 + i;              // 0..127 16B units
            const int row = u >> 3;                  // 0..15
            const int seg = (u & 7) * 16;            // 0..112
            const int sofs = (cc * 16 + row) * 512 + wn * 128 + seg;
            const uint32_t dofs = (uint32_t)(row * 128 + (seg ^ ((row & 7) << 4)));
            cpa16(dst + dofs,        (lastR ? g_Wh : g_Uh) + sofs);
            cpa16(dst + 2048 + dofs, (lastR ? g_Wl : g_Ul) + sofs);
        }
        cp_commit();
    };

    float acc[2][8][4];

    auto do_chunk = [&](int c, uint32_t qb) {
        const uint32_t ak = ((uint32_t)(c * 32) + aseg) ^ axor;
        uint32_t ahi[2][4], alo[2][4];
        ldsm4(ahi[0], aHi + ak);
        ldsm4(ahi[1], aHi + 8192 + ak);
        ldsm4(alo[0], aLo + ak);
        ldsm4(alo[1], aLo + 8192 + ak);
        #pragma unroll
        for (int g = 0; g < 4; g++) {
            uint32_t bh[4], bl[4];
            const uint32_t ba = qb + bRow + (((uint32_t)(g * 32) + bseg) ^ bxor);
            ldsm4t(bh, ba);
            ldsm4t(bl, ba + 2048);
            mma16816(acc[0][2 * g],     ahi[0], bh[0], bh[1]);
            mma16816(acc[1][2 * g],     ahi[1], bh[0], bh[1]);
            mma16816(acc[0][2 * g + 1], ahi[0], bh[2], bh[3]);
            mma16816(acc[1][2 * g + 1], ahi[1], bh[2], bh[3]);
            mma16816(acc[0][2 * g],     alo[0], bh[0], bh[1]);
            mma16816(acc[1][2 * g],     alo[1], bh[0], bh[1]);
            mma16816(acc[0][2 * g + 1], alo[0], bh[2], bh[3]);
            mma16816(acc[1][2 * g + 1], alo[1], bh[2], bh[3]);
            mma16816(acc[0][2 * g],     ahi[0], bl[0], bl[1]);
            mma16816(acc[1][2 * g],     ahi[1], bl[0], bl[1]);
            mma16816(acc[0][2 * g + 1], ahi[0], bl[2], bl[3]);
            mma16816(acc[1][2 * g + 1], ahi[1], bl[2], bl[3]);
        }
    };

    // epilogue: h = relu(proj(col) [+ D]); split to bf16 hi/lo in swizzled smem
    float xs0[4], xs1[4], xs2[4];
    auto load_xs = [&](int col) {
        #pragma unroll
        for (int q = 0; q < 4; q++) {
            const int row = wm * 32 + (q >> 1) * 16 + (q & 1) * 8 + gid;
            const int idx = (b0 + row) * kT + col;
            xs0[q] = __ldg(x0 + idx);
            xs1[q] = __ldg(x1 + idx);
            xs2[q] = __ldg(x2 + idx);
        }
    };
    auto epilogue = [&](bool addD) {
        #pragma unroll
        for (int nt = 0; nt < 8; nt++) {
            const int cb = wn * 64 + nt * 8 + 2 * tig;
            const float4 wA = *reinterpret_cast<const float4*>(smem + SM_WT + cb * 16);
            const float4 wB = *reinterpret_cast<const float4*>(smem + SM_WT + cb * 16 + 16);
            #pragma unroll
            for (int mt = 0; mt < 2; mt++)
            #pragma unroll
            for (int hf = 0; hf < 2; hf++) {
                const int q = mt * 2 + hf;
                float v0 = wA.w + xs0[q] * wA.x + xs1[q] * wA.y + xs2[q] * wA.z;
                float v1 = wB.w + xs0[q] * wB.x + xs1[q] * wB.y + xs2[q] * wB.z;
                if (addD) {
                    v0 += acc[mt][nt][hf * 2];
                    v1 += acc[mt][nt][hf * 2 + 1];
                }
                v0 = fmaxf(v0, 0.f);
                v1 = fmaxf(v1, 0.f);
                const uint32_t hp = cvt_pack(v0, v1);
                const float h0 = __uint_as_float(hp << 16);
                const float h1 = __uint_as_float(hp & 0xFFFF0000u);
                const uint32_t lp = cvt_pack(v0 - h0, v1 - h1);
                const int row = wm * 32 + mt * 16 + hf * 8 + gid;
                const uint32_t off =
                    (uint32_t)(row * 512 + ((cb * 2) ^ ((row & 7) << 4)));
                st32s(sb + SM_HHI + off, hp);
                st32s(sb + SM_HLO + off, lp);
            }
        }
    };

    // ---- prologue ----
    issue_chunk(0);
    issue_chunk(1);
    __syncthreads();                       // proj table visible
    load_xs(kT - 1);
    epilogue(false);                       // h1 = relu(proj(col 78)), h0 = 0
    bar128(1 + wm);                        // h rows wm visible to row-group

    // ---- rounds ----
    #pragma unroll 1
    for (int r = 0; r < NROUND; r++) {
        if (r < NROUND - 1) load_xs(kT - 2 - r);
        #pragma unroll
        for (int mt = 0; mt < 2; mt++)
            #pragma unroll
            for (int nt = 0; nt < 8; nt++)
                #pragma unroll
                for (int e = 0; e < 4; e++) acc[mt][nt][e] = 0.f;

        const int gbase = r * NCH;
        #pragma unroll 2
        for (int c = 0; c < NCH; c++) {
            const int gi = gbase + c;
            if (gi + 2 < TOTAL_CH)
                asm volatile("cp.async.wait_group 1;" ::: "memory");
            else
                asm volatile("cp.async.wait_group 0;" ::: "memory");
            bar64(3 + wn);                 // group: stage (gi&1) ready everywhere
            do_chunk(c, sb + SM_B + (uint32_t)wn * 8192u + (uint32_t)(gi & 1) * 4096u);
            bar64(3 + wn);                 // group: all reads of stage done
            if (gi + 2 < TOTAL_CH) issue_chunk(gi + 2);
        }

        bar128(1 + wm);                    // row-group: A reads of rows wm done
        if (r < NROUND - 1) {
            epilogue(true);                // h_{t+1}
            bar128(1 + wm);                // h rows wm written
        } else {
            // out = D + b_d
            #pragma unroll
            for (int nt = 0; nt < 8; nt++) {
                const int cb = wn * 64 + nt * 8 + 2 * tig;
                const float bd0 = __ldg(bd + cb);
                const float bd1 = __ldg(bd + cb + 1);
                #pragma unroll
                for (int mt = 0; mt < 2; mt++)
                #pragma unroll
                for (int hf = 0; hf < 2; hf++) {
                    const int row = wm * 32 + mt * 16 + hf * 8 + gid;
                    float2 o;
                    o.x = acc[mt][nt][hf * 2]     + bd0;
                    o.y = acc[mt][nt][hf * 2 + 1] + bd1;
                    *reinterpret_cast<float2*>(out + (size_t)(b0 + row) * 256 + cb) = o;
                }
            }
        }
    }
}

extern "C" void kernel_launch(void* const* d_in, const int* in_sizes, int n_in,
                              void* d_out, int out_size) {
    const float* x0   = (const float*)d_in[0];
    const float* x1   = (const float*)d_in[1];
    const float* x2   = (const float*)d_in[2];
    const float* Win  = (const float*)d_in[3];
    const float* U    = (const float*)d_in[4];
    const float* brnn = (const float*)d_in[5];
    const float* Wd   = (const float*)d_in[6];
    const float* bd   = (const float*)d_in[7];
    float* out = (float*)d_out;

    prep_kernel<<<256, 256>>>(U, Wd);

    cudaFuncSetAttribute(rnn_hmma_kernel,
                         cudaFuncAttributeMaxDynamicSharedMemorySize, SMEM_BYTES);
    rnn_hmma_kernel<<<16384 / kBM, kTH, SMEM_BYTES>>>(x0, x1, x2, Win, brnn, bd, out);
}